// round 3
// baseline (speedup 1.0000x reference)
#include <cuda_runtime.h>

// Problem constants
#define Bq 256
#define Tq 4096
#define Nn 8
#define TWO_N 16
#define Hh 64
#define Pp 144          // 2N + 2N^2
#define NBLK 4096       // Bq * (Tq/256)

// Deterministic partial sums: [0:4096) data, [4096:8192) physics
__device__ float g_part[2 * NBLK];

// ---- f32x2 helpers (ptxas never emits FFMA2 from C++; must come from PTX) ----
__device__ __forceinline__ void ffma2(unsigned long long &acc,
                                      unsigned long long a,
                                      unsigned long long b) {
    asm("fma.rn.f32x2 %0, %1, %2, %0;" : "+l"(acc) : "l"(a), "l"(b));
}
__device__ __forceinline__ unsigned long long pack2(float x) {
    unsigned long long u;
    asm("mov.b64 %0, {%1, %1};" : "=l"(u) : "f"(x));
    return u;
}
__device__ __forceinline__ void unpack2(unsigned long long u, float &lo, float &hi) {
    asm("mov.b64 {%0, %1}, %2;" : "=f"(lo), "=f"(hi) : "l"(u));
}
__device__ __forceinline__ float tanh_fast(float x) {
    float y;
    asm("tanh.approx.f32 %0, %1;" : "=f"(y) : "f"(x));
    return y;
}

__global__ __launch_bounds__(256)
void pinn_main(const float* __restrict__ t,
               const float* __restrict__ x_target,
               const float* __restrict__ params_pred,
               const float* __restrict__ W1,
               const float* __restrict__ b1,
               const float* __restrict__ W2,
               const float* __restrict__ b2)
{
    __shared__ __align__(16) unsigned long long sW2[Hh * 8];  // 64 rows x 8 float2
    __shared__ float2 sWb[Hh];        // (W1[k], b1[k])
    __shared__ float  sb2[TWO_N];
    __shared__ float  sPar[Pp];       // g[0:8) mu[8:16) Pi[16:80) Gamma[80:144)
    __shared__ float2 red[256];

    const int tid = threadIdx.x;
    const int b   = blockIdx.x >> 4;                  // 16 t-chunks per batch
    const int ti  = ((blockIdx.x & 15) << 8) | tid;   // t index in [0,4096)

    // Stage weights & per-batch params into SMEM
    const unsigned long long* W2u = (const unsigned long long*)W2; // W2 row-major [64][16]
    for (int i = tid; i < Hh * 8; i += 256) sW2[i] = W2u[i];
    if (tid < Hh)    sWb[tid] = make_float2(W1[tid], b1[tid]);
    if (tid < TWO_N) sb2[tid] = b2[tid];
    if (tid < Pp)    sPar[tid] = params_pred[(size_t)b * Pp + tid];
    __syncthreads();

    const float tv = t[(size_t)b * Tq + ti];

    // latent / dlatent accumulators, 8 x (f32x2) each
    unsigned long long lat[8], dla[8];
    #pragma unroll
    for (int j = 0; j < 8; j++) { lat[j] = 0ull; dla[j] = 0ull; }

    // MLP: h = tanh(tv*W1+b1); latent = h@W2; dlatent = ((1-h^2)*W1)@W2
    #pragma unroll 8
    for (int k = 0; k < Hh; k++) {
        float2 wb = sWb[k];
        float z  = fmaf(tv, wb.x, wb.y);
        float h  = tanh_fast(z);
        float dh = fmaf(-h * h, wb.x, wb.x);          // (1-h^2)*W1[k]
        unsigned long long h2  = pack2(h);
        unsigned long long dh2 = pack2(dh);
        const unsigned long long* wr = &sW2[k * 8];
        #pragma unroll
        for (int j = 0; j < 8; j++) {
            ffma2(lat[j], h2,  wr[j]);
            ffma2(dla[j], dh2, wr[j]);
        }
    }

    float s[TWO_N], ds[TWO_N];
    #pragma unroll
    for (int j = 0; j < 8; j++) {
        float lx, ly, dx_, dy_;
        unpack2(lat[j], lx, ly);
        unpack2(dla[j], dx_, dy_);
        s[2 * j]      = lx + sb2[2 * j];
        s[2 * j + 1]  = ly + sb2[2 * j + 1];
        ds[2 * j]     = dx_;
        ds[2 * j + 1] = dy_;
    }

    // Observables + JVP through relu
    float av[Nn], xv[Nn], dsa[Nn], dsx[Nn];
    #pragma unroll
    for (int i = 0; i < Nn; i++) {
        av[i]  = s[i];
        dsa[i] = ds[i];
        float qm = s[Nn + i] - sPar[Nn + i];          // q - mu
        bool pos = qm > 0.0f;
        xv[i]  = pos ? qm : 0.0f;
        dsx[i] = pos ? ds[Nn + i] : 0.0f;
    }

    // Data loss: sum_j (state_j - x_target[b,j,ti])^2
    const float* xt = x_target + ((size_t)b * TWO_N) * Tq + ti;
    float dacc = 0.f;
    #pragma unroll
    for (int j = 0; j < Nn; j++) { float d = av[j] - xt[j * Tq];        dacc = fmaf(d, d, dacc); }
    #pragma unroll
    for (int j = 0; j < Nn; j++) { float d = xv[j] - xt[(Nn + j) * Tq]; dacc = fmaf(d, d, dacc); }

    // Physics loss: (dstate - rhs)^2
    float pacc = 0.f;
    #pragma unroll
    for (int i = 0; i < Nn; i++) {
        float da = sPar[i] - av[i];                   // g - a
        #pragma unroll
        for (int j = 0; j < Nn; j++) da = fmaf(sPar[16 + i * 8 + j], xv[j], da);   // + Pi@x
        float gm = 0.f;
        #pragma unroll
        for (int j = 0; j < Nn; j++) gm = fmaf(sPar[80 + i * 8 + j], av[j], gm);   // Gamma@a
        float dx = gm * (sPar[Nn + i] - xv[i]);       // * (mu - x)
        float e1 = dsa[i] - da;
        float e2 = dsx[i] - dx;
        pacc = fmaf(e1, e1, fmaf(e2, e2, pacc));
    }

    // Deterministic block tree reduction
    red[tid] = make_float2(dacc, pacc);
    __syncthreads();
    #pragma unroll
    for (int stp = 128; stp > 0; stp >>= 1) {
        if (tid < stp) {
            red[tid].x += red[tid + stp].x;
            red[tid].y += red[tid + stp].y;
        }
        __syncthreads();
    }
    if (tid == 0) {
        g_part[blockIdx.x]        = red[0].x;
        g_part[NBLK + blockIdx.x] = red[0].y;
    }
}

__global__ __launch_bounds__(1024)
void pinn_reduce(const float* __restrict__ params_pred,
                 const float* __restrict__ params_target,
                 const float* __restrict__ ic_pred,
                 const float* __restrict__ ic_target,
                 float* __restrict__ out)
{
    __shared__ float sd[1024], sp[1024], ss[1024];
    const int tid = threadIdx.x;
    float d = 0.f, p = 0.f, sup = 0.f;
    for (int i = tid; i < NBLK; i += 1024) { d += g_part[i]; p += g_part[NBLK + i]; }
    for (int i = tid; i < Bq * Pp; i += 1024) {
        float e = params_pred[i] - params_target[i];
        sup = fmaf(e, e, sup);
    }
    for (int i = tid; i < Bq * TWO_N; i += 1024) {
        float e = ic_pred[i] - ic_target[i];
        sup = fmaf(e, e, sup);
    }
    sd[tid] = d; sp[tid] = p; ss[tid] = sup;
    __syncthreads();
    #pragma unroll
    for (int stp = 512; stp > 0; stp >>= 1) {
        if (tid < stp) {
            sd[tid] += sd[tid + stp];
            sp[tid] += sp[tid + stp];
            ss[tid] += ss[tid + stp];
        }
        __syncthreads();
    }
    if (tid == 0) {
        const float inv_dp = 1.0f / 16777216.0f;   // B * 2N * T
        const float inv_s  = 1.0f / 40960.0f;      // B * (P + 2N)
        out[0] = (sd[0] + sp[0]) * inv_dp + ss[0] * inv_s;
    }
}

extern "C" void kernel_launch(void* const* d_in, const int* in_sizes, int n_in,
                              void* d_out, int out_size)
{
    const float* t             = (const float*)d_in[0];
    const float* x_target      = (const float*)d_in[1];
    const float* params_pred   = (const float*)d_in[2];
    const float* params_target = (const float*)d_in[3];
    const float* ic_pred       = (const float*)d_in[4];
    const float* ic_target     = (const float*)d_in[5];
    const float* W1            = (const float*)d_in[6];
    const float* b1            = (const float*)d_in[7];
    const float* W2            = (const float*)d_in[8];
    const float* b2            = (const float*)d_in[9];
    float* out = (float*)d_out;

    pinn_main<<<NBLK, 256>>>(t, x_target, params_pred, W1, b1, W2, b2);
    pinn_reduce<<<1, 1024>>>(params_pred, params_target, ic_pred, ic_target, out);
}